// round 5
// baseline (speedup 1.0000x reference)
#include <cuda_runtime.h>
#include <cstdint>

#define BB    4
#define LL    1024
#define DIMM  512
#define NH    8
#define HDIM  64
#define KNEED 716          // max(1, int(1024 * 0.7))
#define NEGV  (-1e9f)

typedef unsigned long long ull;

// ---------------- scratch (static device globals; no allocation) ----------------
__device__ float g_q [BB*NH*LL*HDIM];   // (b,h,i,d)
__device__ float g_kt[BB*NH*HDIM*LL];   // (b,h,d,j)  transposed K
__device__ float g_v [BB*NH*LL*HDIM];   // (b,h,j,d)
__device__ float g_ao[BB*LL*DIMM];      // (b,i,h*64+d) attention output
__device__ float g_pw[BB*3];            // pattern weights per batch
__device__ float g_part[BB*32*DIMM];    // pooling partials

// ---------------- f32x2 packed helpers ----------------
__device__ __forceinline__ ull pk2(float a, float b) {
    ull r; asm("mov.b64 %0,{%1,%2};" : "=l"(r) : "f"(a), "f"(b)); return r;
}
__device__ __forceinline__ void fma2(ull& d, ull a, ull b) {
    asm("fma.rn.f32x2 %0, %1, %2, %0;" : "+l"(d) : "l"(a), "l"(b));
}
__device__ __forceinline__ ull mul2(ull a, ull b) {
    ull r; asm("mul.rn.f32x2 %0, %1, %2;" : "=l"(r) : "l"(a), "l"(b)); return r;
}
__device__ __forceinline__ ull add2(ull a, ull b) {
    ull r; asm("add.rn.f32x2 %0, %1, %2;" : "=l"(r) : "l"(a), "l"(b)); return r;
}
__device__ __forceinline__ float2 upk(ull v) {
    float2 r; asm("mov.b64 {%0,%1},%2;" : "=f"(r.x), "=f"(r.y) : "l"(v)); return r;
}
__device__ __forceinline__ unsigned ordkey(float s) {
    unsigned u = __float_as_uint(s);
    return (u & 0x80000000u) ? ~u : (u | 0x80000000u);
}

// ======================= K1: 128x128x16 GEMM, f32x2, duplicated-A smem, 1-sync ping-pong ===========
template<int MODE>
__global__ void __launch_bounds__(256, 2) gemm128(const float* __restrict__ A,
                                                  const float* __restrict__ W,
                                                  const float* __restrict__ bias,
                                                  float* __restrict__ out) {
    __shared__ ull   As2[2][16][132];   // A values duplicated (a,a); row stride 1056B (16B mult)
    __shared__ float Bs [2][16][132];   // row stride 528B (16B mult)
    const int m0 = blockIdx.y * 128, n0 = blockIdx.x * 128;
    const int tid = threadIdx.x;
    const int tx = tid & 15, ty = tid >> 4;
    const float* Ap = (MODE == 1) ? g_ao : A;

    ull acc[8][4];
    #pragma unroll
    for (int r = 0; r < 8; r++)
        #pragma unroll
        for (int c = 0; c < 4; c++) acc[r][c] = 0ull;

    float4 pa[2], pb[2];

    auto ldT = [&](int k0) {
        #pragma unroll
        for (int i = 0; i < 2; i++) {
            int idx = tid + i * 256;
            int r = idx >> 2, kq = (idx & 3) * 4;
            pa[i] = *(const float4*)(Ap + (size_t)(m0 + r) * 512 + k0 + kq);
            pb[i] = *(const float4*)(W  + (size_t)(n0 + r) * 512 + k0 + kq);
        }
    };
    auto stT = [&](int s) {
        #pragma unroll
        for (int i = 0; i < 2; i++) {
            int idx = tid + i * 256;
            int r = idx >> 2, kq = (idx & 3) * 4;
            As2[s][kq+0][r] = pk2(pa[i].x, pa[i].x);
            As2[s][kq+1][r] = pk2(pa[i].y, pa[i].y);
            As2[s][kq+2][r] = pk2(pa[i].z, pa[i].z);
            As2[s][kq+3][r] = pk2(pa[i].w, pa[i].w);
            Bs[s][kq+0][r] = pb[i].x; Bs[s][kq+1][r] = pb[i].y;
            Bs[s][kq+2][r] = pb[i].z; Bs[s][kq+3][r] = pb[i].w;
        }
    };

    ldT(0); stT(0); __syncthreads();
    ldT(16);

    for (int kt = 0; kt < 32; kt++) {
        if (kt < 31) stT((kt + 1) & 1);
        if (kt < 30) ldT((kt + 2) * 16);
        const int st = kt & 1;
        #pragma unroll
        for (int kk = 0; kk < 16; kk++) {
            ulonglong2 b0 = *(const ulonglong2*)&Bs[st][kk][tx * 4];
            ulonglong2 b1 = *(const ulonglong2*)&Bs[st][kk][64 + tx * 4];
            ulonglong2 q01 = *(const ulonglong2*)&As2[st][kk][ty * 8];
            ulonglong2 q23 = *(const ulonglong2*)&As2[st][kk][ty * 8 + 2];
            ulonglong2 q45 = *(const ulonglong2*)&As2[st][kk][ty * 8 + 4];
            ulonglong2 q67 = *(const ulonglong2*)&As2[st][kk][ty * 8 + 6];
            ull qb[8] = {q01.x, q01.y, q23.x, q23.y, q45.x, q45.y, q67.x, q67.y};
            #pragma unroll
            for (int r = 0; r < 8; r++) {
                fma2(acc[r][0], qb[r], b0.x); fma2(acc[r][1], qb[r], b0.y);
                fma2(acc[r][2], qb[r], b1.x); fma2(acc[r][3], qb[r], b1.y);
            }
        }
        if (kt < 31) __syncthreads();
    }

    #pragma unroll
    for (int r = 0; r < 8; r++) {
        int m = m0 + ty * 8 + r;
        #pragma unroll
        for (int c = 0; c < 4; c++) {
            int n = n0 + ((c < 2) ? (tx * 4 + 2 * c) : (64 + tx * 4 + 2 * (c - 2)));
            if (MODE == 0) {
                int b = m >> 10, i = m & 1023;
                float2 v = upk(acc[r][c]);
                if (n < 512) {
                    int hh = n >> 6, d = n & 63;
                    float* p = g_q + (((size_t)(b * 8 + hh) << 10) + i) * 64 + d;
                    p[0] = v.x; p[1] = v.y;
                } else if (n < 1024) {
                    int nn = n - 512, hh = nn >> 6, d = nn & 63;
                    float* p = g_kt + ((size_t)(b * 8 + hh) * 64 + d) * 1024 + i;
                    p[0] = v.x; p[1024] = v.y;
                } else {
                    int nn = n - 1024, hh = nn >> 6, d = nn & 63;
                    float* p = g_v + (((size_t)(b * 8 + hh) << 10) + i) * 64 + d;
                    p[0] = v.x; p[1] = v.y;
                }
            } else {
                ull bv = *(const ull*)(bias + n);
                *(ull*)(out + (size_t)m * 512 + n) = add2(acc[r][c], bv);
            }
        }
    }
}

// ======================= K2: pooling + selector =======================
__global__ void __launch_bounds__(512) pool_kernel(const float* __restrict__ x) {
    const int b = blockIdx.x >> 5, s = blockIdx.x & 31;
    const int tid = threadIdx.x;
    const float* xb = x + ((size_t)b * 1024 + s * 32) * 512;
    float sum = 0.f;
    #pragma unroll 8
    for (int i = 0; i < 32; i++) sum += xb[(size_t)i * 512 + tid];
    g_part[(b * 32 + s) * 512 + tid] = sum;
}

__global__ void __launch_bounds__(512) selector(const float* __restrict__ W1,
                                                const float* __restrict__ b1,
                                                const float* __restrict__ W2,
                                                const float* __restrict__ b2,
                                                const float* __restrict__ logtau) {
    __shared__ float pooled[512];
    __shared__ float hh[256];
    __shared__ float lg[3];
    const int b = blockIdx.x, tid = threadIdx.x;
    {
        float s = 0.f;
        #pragma unroll
        for (int p = 0; p < 32; p++) s += g_part[(b * 32 + p) * 512 + tid];
        pooled[tid] = s * (1.0f / 1024.0f);
    }
    __syncthreads();
    if (tid < 256) {
        float a = b1[tid];
        const float* wr = W1 + (size_t)tid * 512;
        #pragma unroll 4
        for (int d = 0; d < 512; d++) a = fmaf(pooled[d], wr[d], a);
        hh[tid] = a > 0.f ? a : 0.f;
    }
    __syncthreads();
    if (tid < 3) {
        float a = b2[tid];
        const float* wr = W2 + (size_t)tid * 256;
        for (int d = 0; d < 256; d++) a = fmaf(hh[d], wr[d], a);
        lg[tid] = a;
    }
    __syncthreads();
    if (tid == 0) {
        float tau = expf(logtau[0]);
        tau = fminf(fmaxf(tau, 1e-4f), 10.0f);
        float l0 = lg[0] / tau, l1 = lg[1] / tau, l2 = lg[2] / tau;
        float mx = fmaxf(l0, fmaxf(l1, l2));
        float e0 = expf(l0 - mx), e1 = expf(l1 - mx), e2 = expf(l2 - mx);
        float inv = 1.0f / (e0 + e1 + e2);
        g_pw[b * 3 + 0] = e0 * inv;
        g_pw[b * 3 + 1] = e1 * inv;
        g_pw[b * 3 + 2] = e2 * inv;
    }
}

// ======================= K3: fused attention (16 rows / block, 256 threads, 2 blocks/SM) ===========
struct SmemAttn {
    ull   qT2[64][18];            // 9.2 KB  q duplicated pairs, row 144B
    float sc[16][1032];           // 66 KB   (row 4128B -> bank shift between rows)
    union {
        float kbuf[2][4][1024];                                  // 32 KB
        struct { float vbuf[2][32][64]; ull red[128][2][4]; } av; // 16+8 KB
        unsigned hist[8][256];                                   // 8 KB
    } u;
    unsigned thr[16];
    float    rowmax[16];
    float    rowsum[16];
    int      anyf[16];
};

__global__ void __launch_bounds__(256, 2) attn_kernel(const int* __restrict__ mask,
                                                      const float* __restrict__ sparse_w,
                                                      const float* __restrict__ sparse_b) {
    extern __shared__ char smraw[];
    SmemAttn* sm = (SmemAttn*)smraw;
    const int tid = threadIdx.x;
    const int i0 = blockIdx.x * 16;
    const int h  = blockIdx.y;
    const int b  = blockIdx.z;
    const int bh = b * 8 + h;
    const float* qg  = g_q  + (size_t)bh * 1024 * 64;
    const float* ktg = g_kt + (size_t)bh * 64 * 1024;
    const float* vg  = g_v  + (size_t)bh * 1024 * 64;

    const float pw0 = g_pw[b * 3 + 0], pw1 = g_pw[b * 3 + 1], pw2 = g_pw[b * 3 + 2];
    const float wsp = sparse_w[h], bsp = sparse_b[h];
    const bool need_smask = (((pw1 > 0.05f) != (pw1 + pw2 > 0.05f)) ||
                             ((pw0 + pw1 > 0.05f) != (pw0 + pw1 + pw2 > 0.05f)));

    // ---- load qT2 (transposed, duplicated q tile) ----
    #pragma unroll
    for (int it = 0; it < 4; it++) {
        int idx = tid + it * 256;          // 0..1023
        int r = idx >> 6, d = idx & 63;
        float qv = qg[(size_t)(i0 + r) * 64 + d];
        sm->qT2[d][r] = pk2(qv, qv);
    }

    // ---- phase 1: scores (16 rows x 1024 cols), thread tile 4 rows x 16 cols (4 quarters) ----
    const int rg = tid >> 6;     // 0..3 -> rows rg*4..+4
    const int cg = tid & 63;     // cols cg*4 + qq*256
    ull acc[4][8];
    #pragma unroll
    for (int r = 0; r < 4; r++)
        #pragma unroll
        for (int c = 0; c < 8; c++) acc[r][c] = 0ull;

    float4 kreg[4];
    auto ldK = [&](int c) {
        #pragma unroll
        for (int it = 0; it < 4; it++) {
            int idx = tid + it * 256;          // 1024 float4 slots: 4 d x 256
            int d = idx >> 8, jf = (idx & 255) * 4;
            kreg[it] = *(const float4*)(ktg + (size_t)(c * 4 + d) * 1024 + jf);
        }
    };
    auto stK = [&](int s) {
        #pragma unroll
        for (int it = 0; it < 4; it++) {
            int idx = tid + it * 256;
            int d = idx >> 8, jf = (idx & 255) * 4;
            *(float4*)&sm->u.kbuf[s][d][jf] = kreg[it];
        }
    };

    ldK(0); stK(0); __syncthreads();
    ldK(1);
    for (int c = 0; c < 16; c++) {
        if (c < 15) stK((c + 1) & 1);
        if (c < 14) ldK(c + 2);
        const float (*kb)[1024] = sm->u.kbuf[c & 1];
        #pragma unroll
        for (int dd = 0; dd < 4; dd++) {
            int d = c * 4 + dd;
            ulonglong2 q01 = *(const ulonglong2*)&sm->qT2[d][rg * 4];
            ulonglong2 q23 = *(const ulonglong2*)&sm->qT2[d][rg * 4 + 2];
            ull qb[4] = {q01.x, q01.y, q23.x, q23.y};
            #pragma unroll
            for (int qq = 0; qq < 4; qq++) {
                ulonglong2 kp = *(const ulonglong2*)&kb[dd][qq * 256 + cg * 4];
                #pragma unroll
                for (int r = 0; r < 4; r++) {
                    fma2(acc[r][qq * 2],     qb[r], kp.x);
                    fma2(acc[r][qq * 2 + 1], qb[r], kp.y);
                }
            }
        }
        if (c < 15) __syncthreads();
    }
    {
        const ull sc2 = pk2(0.125f, 0.125f);
        #pragma unroll
        for (int r = 0; r < 4; r++)
            #pragma unroll
            for (int qq = 0; qq < 4; qq++) {
                ulonglong2 o;
                o.x = mul2(acc[r][qq * 2], sc2);
                o.y = mul2(acc[r][qq * 2 + 1], sc2);
                *(ulonglong2*)&sm->sc[rg * 4 + r][qq * 256 + cg * 4] = o;
            }
    }
    __syncthreads();

    // ---- phase 2: exact kth-largest per row (radix select), 8 warps x 2 rows ----
    if (need_smask) {
        const int wq = tid >> 5, lane = tid & 31;
        for (int rr = 0; rr < 2; rr++) {
            const int r = wq * 2 + rr;
            unsigned prefix = 0;
            int kneed = KNEED;
            #pragma unroll
            for (int pass = 0; pass < 4; pass++) {
                const int shift = 24 - 8 * pass;
                #pragma unroll
                for (int q = 0; q < 8; q++) sm->u.hist[wq][lane * 8 + q] = 0u;
                __syncwarp();
                for (int t = 0; t < 32; t++) {
                    int j = lane + t * 32;
                    float s = fmaf(sm->sc[r][j], wsp, bsp);
                    unsigned u = ordkey(s);
                    bool cand;
                    if (pass == 0) cand = true;
                    else           cand = (((u ^ prefix) >> (shift + 8)) == 0u);
                    int bucket = cand ? (int)((u >> shift) & 255u) : 256;
                    unsigned mm = __match_any_sync(0xffffffffu, bucket);
                    if ((__ffs(mm) - 1) == lane && bucket < 256)
                        atomicAdd(&sm->u.hist[wq][bucket], (unsigned)__popc(mm));
                }
                __syncwarp();
                const int base = 255 - lane * 8;
                int c[8]; int loc = 0;
                #pragma unroll
                for (int q = 0; q < 8; q++) { c[q] = (int)sm->u.hist[wq][base - q]; loc += c[q]; }
                int pre = loc;
                #pragma unroll
                for (int o = 1; o < 32; o <<= 1) {
                    int v = __shfl_up_sync(0xffffffffu, pre, o);
                    if (lane >= o) pre += v;
                }
                const int excl = pre - loc;
                const bool hit = (excl < kneed) && (kneed <= pre);
                const unsigned hb = __ballot_sync(0xffffffffu, hit);
                const int hl = __ffs(hb) - 1;
                int bsel = 0, kn2 = 0;
                if (hit) {
                    int rem = kneed - excl;
                    #pragma unroll
                    for (int q = 0; q < 8; q++) {
                        if (rem <= c[q]) { bsel = base - q; kn2 = rem; break; }
                        rem -= c[q];
                    }
                }
                bsel = __shfl_sync(0xffffffffu, bsel, hl);
                kn2  = __shfl_sync(0xffffffffu, kn2,  hl);
                prefix |= ((unsigned)bsel) << shift;
                kneed = kn2;
                __syncwarp();
            }
            if (lane == 0) sm->thr[r] = prefix;
        }
    } else {
        if (tid < 16) sm->thr[tid] = 0u;
    }
    __syncthreads();

    // ---- phase 3: combined mask + fallback + softmax (vectorized) ----
    const int r3 = tid >> 4;   // 0..15
    const int c3 = tid & 15;
    {
        const int* mrow = mask + b * 1024;
        const unsigned thrv = sm->thr[r3];
        const int ii = i0 + r3;
        float locmax = -3.0e38f;
        int any = 0;
        #pragma unroll 4
        for (int t = 0; t < 16; t++) {
            int j = c3 * 4 + t * 64;
            float4 f = *(const float4*)&sm->sc[r3][j];
            int4 mm4 = *(const int4*)(mrow + j);
            float fv[4] = {f.x, f.y, f.z, f.w};
            int   mv[4] = {mm4.x, mm4.y, mm4.z, mm4.w};
            #pragma unroll
            for (int e = 0; e < 4; e++) {
                int je = j + e;
                float s = fmaf(fv[e], wsp, bsp);
                float smv = (ordkey(s) >= thrv) ? 1.0f : 0.0f;
                float lcl = (je >= ii - 16 && je <= ii + 16) ? 1.0f : 0.0f;
                float comb = fmaf(pw0, lcl, fmaf(pw2, smv, pw1));
                bool keep = (comb > 0.05f) && (mv[e] != 0);
                if (keep) { locmax = fmaxf(locmax, fv[e]); any = 1; }
                else      fv[e] = NEGV;
            }
            float4 o = {fv[0], fv[1], fv[2], fv[3]};
            *(float4*)&sm->sc[r3][j] = o;
        }
        #pragma unroll
        for (int o = 8; o; o >>= 1) {
            locmax = fmaxf(locmax, __shfl_down_sync(0xffffffffu, locmax, o, 16));
            any   |= __shfl_down_sync(0xffffffffu, any, o, 16);
        }
        if (c3 == 0) { sm->rowmax[r3] = locmax; sm->anyf[r3] = any; }
    }
    __syncthreads();
    if (tid < 16) {
        if (!sm->anyf[tid]) { sm->sc[tid][0] = 0.0f; sm->rowmax[tid] = 0.0f; }
    }
    __syncthreads();
    {
        const float rmax = sm->rowmax[r3];
        float lsum = 0.f;
        #pragma unroll 4
        for (int t = 0; t < 16; t++) {
            int j = c3 * 4 + t * 64;
            float4 f = *(const float4*)&sm->sc[r3][j];
            f.x = __expf(f.x - rmax); f.y = __expf(f.y - rmax);
            f.z = __expf(f.z - rmax); f.w = __expf(f.w - rmax);
            *(float4*)&sm->sc[r3][j] = f;
            lsum += (f.x + f.y) + (f.z + f.w);
        }
        #pragma unroll
        for (int o = 8; o; o >>= 1)
            lsum += __shfl_down_sync(0xffffffffu, lsum, o, 16);
        if (c3 == 0) sm->rowsum[r3] = lsum;
    }

    // ---- phase 4: AV, thread tile 2 rows x 4 cols, j split 2-way, 32 chunks of 32 j ----
    const int cgrp = tid & 15;          // cols cgrp*4..+3
    const int rgrp = (tid >> 4) & 7;    // rows rgrp*2..+2
    const int jh   = tid >> 7;          // 0..1 j-slice
    ull a2[2][2];
    a2[0][0] = a2[0][1] = a2[1][0] = a2[1][1] = 0ull;

    float4 vreg[2];
    auto ldV = [&](int c) {
        #pragma unroll
        for (int it = 0; it < 2; it++) {
            int idx = tid + it * 256;              // 512 float4 slots: 32 j x 16
            int jj = idx >> 4, df = (idx & 15) * 4;
            vreg[it] = *(const float4*)(vg + (size_t)(c * 32 + jj) * 64 + df);
        }
    };
    auto stV = [&](int s) {
        #pragma unroll
        for (int it = 0; it < 2; it++) {
            int idx = tid + it * 256;
            int jj = idx >> 4, df = (idx & 15) * 4;
            *(float4*)&sm->u.av.vbuf[s][jj][df] = vreg[it];
        }
    };

    ldV(0); stV(0); __syncthreads();   // also publishes phase-3 prob writes
    ldV(1);
    for (int c = 0; c < 32; c++) {
        if (c < 31) stV((c + 1) & 1);
        if (c < 30) ldV(c + 2);
        const float (*vb)[64] = sm->u.av.vbuf[c & 1];
        #pragma unroll
        for (int q = 0; q < 4; q++) {
            const int jl = jh * 16 + q * 4;
            const int j  = c * 32 + jl;
            float4 p0 = *(const float4*)&sm->sc[rgrp * 2][j];
            float4 p1 = *(const float4*)&sm->sc[rgrp * 2 + 1][j];
            float pa4[4] = {p0.x, p0.y, p0.z, p0.w};
            float pb4[4] = {p1.x, p1.y, p1.z, p1.w};
            #pragma unroll
            for (int t = 0; t < 4; t++) {
                ulonglong2 vv = *(const ulonglong2*)&vb[jl + t][cgrp * 4];
                ull pa = pk2(pa4[t], pa4[t]);
                ull pb = pk2(pb4[t], pb4[t]);
                fma2(a2[0][0], pa, vv.x); fma2(a2[0][1], pa, vv.y);
                fma2(a2[1][0], pb, vv.x); fma2(a2[1][1], pb, vv.y);
            }
        }
        if (c < 31) __syncthreads();
    }
    // j-split reduction via smem (red region disjoint from vbuf)
    #pragma unroll
    for (int r = 0; r < 2; r++) {
        sm->u.av.red[rgrp * 16 + cgrp][jh][r * 2 + 0] = a2[r][0];
        sm->u.av.red[rgrp * 16 + cgrp][jh][r * 2 + 1] = a2[r][1];
    }
    __syncthreads();
    #pragma unroll
    for (int oo = 0; oo < 2; oo++) {
        int o = tid + oo * 256;        // 0..511 output ull (16 rows x 32 col-ull)
        int row = o >> 5, cu = o & 31;
        int rg2 = row >> 1, rr = row & 1, cg2 = cu >> 1, uc = cu & 1;
        ull s = add2(sm->u.av.red[rg2 * 16 + cg2][0][rr * 2 + uc],
                     sm->u.av.red[rg2 * 16 + cg2][1][rr * 2 + uc]);
        float inv = 1.0f / sm->rowsum[row];
        float2 fo = upk(s);
        float* op = g_ao + ((size_t)(b * 1024 + i0 + row)) * 512 + h * 64 + cg2 * 4 + uc * 2;
        op[0] = fo.x * inv; op[1] = fo.y * inv;
    }
}

// ======================= launch =======================
extern "C" void kernel_launch(void* const* d_in, const int* in_sizes, int n_in,
                              void* d_out, int out_size) {
    const float* x      = (const float*)d_in[0];
    const int*   mask   = (const int*)  d_in[1];
    const float* Wqkv   = (const float*)d_in[2];
    const float* Wproj  = (const float*)d_in[3];
    const float* bproj  = (const float*)d_in[4];
    const float* Wsel1  = (const float*)d_in[5];
    const float* bsel1  = (const float*)d_in[6];
    const float* Wsel2  = (const float*)d_in[7];
    const float* bsel2  = (const float*)d_in[8];
    const float* logtau = (const float*)d_in[9];
    const float* sw     = (const float*)d_in[10];
    const float* sb     = (const float*)d_in[11];
    float* out = (float*)d_out;

    static int smem_set = 0;
    if (!smem_set) {
        cudaFuncSetAttribute(attn_kernel, cudaFuncAttributeMaxDynamicSharedMemorySize,
                             (int)sizeof(SmemAttn));
        smem_set = 1;
    }

    gemm128<0><<<dim3(12, 32), 256>>>(x, Wqkv, nullptr, nullptr);
    pool_kernel<<<128, 512>>>(x);
    selector<<<4, 512>>>(Wsel1, bsel1, Wsel2, bsel2, logtau);
    attn_kernel<<<dim3(64, 8, 4), 256, sizeof(SmemAttn)>>>(mask, sw, sb);
    gemm128<1><<<dim3(4, 32), 256>>>(nullptr, Wproj, bproj, out);
}

// round 6
// speedup vs baseline: 1.0326x; 1.0326x over previous
#include <cuda_runtime.h>
#include <cstdint>

#define BB    4
#define LL    1024
#define DIMM  512
#define NH    8
#define HDIM  64
#define KNEED 716          // max(1, int(1024 * 0.7))
#define NEGV  (-1e9f)

typedef unsigned long long ull;

// ---------------- scratch (static device globals; no allocation) ----------------
__device__ float g_q [BB*NH*LL*HDIM];   // (b,h,i,d)
__device__ float g_kt[BB*NH*HDIM*LL];   // (b,h,d,j)  transposed K
__device__ float g_v [BB*NH*LL*HDIM];   // (b,h,j,d)
__device__ float g_ao[BB*LL*DIMM];      // (b,i,h*64+d) attention output
__device__ float g_pw[BB*3];            // pattern weights per batch
__device__ float g_part[BB*8*DIMM];     // pooling partials
__device__ float g_sc[BB*NH*LL*LL];     // 134MB score/prob buffer
__device__ float g_inv[BB*NH*LL];       // per-row 1/softmax-sum

// ---------------- f32x2 packed helpers ----------------
__device__ __forceinline__ ull pk2(float a, float b) {
    ull r; asm("mov.b64 %0,{%1,%2};" : "=l"(r) : "f"(a), "f"(b)); return r;
}
__device__ __forceinline__ void fma2(ull& d, ull a, ull b) {
    asm("fma.rn.f32x2 %0, %1, %2, %0;" : "+l"(d) : "l"(a), "l"(b));
}
__device__ __forceinline__ ull mul2(ull a, ull b) {
    ull r; asm("mul.rn.f32x2 %0, %1, %2;" : "=l"(r) : "l"(a), "l"(b)); return r;
}
__device__ __forceinline__ ull add2(ull a, ull b) {
    ull r; asm("add.rn.f32x2 %0, %1, %2;" : "=l"(r) : "l"(a), "l"(b)); return r;
}
__device__ __forceinline__ float2 upk(ull v) {
    float2 r; asm("mov.b64 {%0,%1},%2;" : "=f"(r.x), "=f"(r.y) : "l"(v)); return r;
}
__device__ __forceinline__ unsigned ordkey(float s) {
    unsigned u = __float_as_uint(s);
    return (u & 0x80000000u) ? ~u : (u | 0x80000000u);
}

// ======================= K1: 128x128x16 GEMM (R4-proven), MODE 0=qkv scatter, 1=proj ============
template<int MODE>
__global__ void __launch_bounds__(256) gemm128(const float* __restrict__ A,
                                               const float* __restrict__ W,
                                               const float* __restrict__ bias,
                                               float* __restrict__ out) {
    __shared__ float As[16][132];
    __shared__ float Bs[16][132];
    const int m0 = blockIdx.y * 128, n0 = blockIdx.x * 128;
    const int tid = threadIdx.x;
    const int tx = tid & 15, ty = tid >> 4;
    const float* Ap = (MODE == 1) ? g_ao : A;

    ull acc[8][4];
    #pragma unroll
    for (int r = 0; r < 8; r++)
        #pragma unroll
        for (int c = 0; c < 4; c++) acc[r][c] = 0ull;

    float4 pa[2], pb[2];
    #pragma unroll
    for (int i = 0; i < 2; i++) {
        int idx = tid + i * 256;
        int r = idx >> 2, kq = (idx & 3) * 4;
        pa[i] = *(const float4*)(Ap + (size_t)(m0 + r) * 512 + kq);
        pb[i] = *(const float4*)(W  + (size_t)(n0 + r) * 512 + kq);
    }

    for (int k0 = 0; k0 < 512; k0 += 16) {
        #pragma unroll
        for (int i = 0; i < 2; i++) {
            int idx = tid + i * 256;
            int r = idx >> 2, kq = (idx & 3) * 4;
            As[kq+0][r] = pa[i].x; As[kq+1][r] = pa[i].y; As[kq+2][r] = pa[i].z; As[kq+3][r] = pa[i].w;
            Bs[kq+0][r] = pb[i].x; Bs[kq+1][r] = pb[i].y; Bs[kq+2][r] = pb[i].z; Bs[kq+3][r] = pb[i].w;
        }
        __syncthreads();
        if (k0 + 16 < 512) {
            #pragma unroll
            for (int i = 0; i < 2; i++) {
                int idx = tid + i * 256;
                int r = idx >> 2, kq = (idx & 3) * 4;
                pa[i] = *(const float4*)(Ap + (size_t)(m0 + r) * 512 + k0 + 16 + kq);
                pb[i] = *(const float4*)(W  + (size_t)(n0 + r) * 512 + k0 + 16 + kq);
            }
        }
        #pragma unroll
        for (int kk = 0; kk < 16; kk++) {
            float4 ba = *(const float4*)&Bs[kk][tx * 4];
            float4 bb = *(const float4*)&Bs[kk][64 + tx * 4];
            ull kp0 = pk2(ba.x, ba.y), kp1 = pk2(ba.z, ba.w);
            ull kp2 = pk2(bb.x, bb.y), kp3 = pk2(bb.z, bb.w);
            float4 av0 = *(const float4*)&As[kk][ty * 8];
            float4 av1 = *(const float4*)&As[kk][ty * 8 + 4];
            float am[8] = {av0.x, av0.y, av0.z, av0.w, av1.x, av1.y, av1.z, av1.w};
            #pragma unroll
            for (int r = 0; r < 8; r++) {
                ull ab = pk2(am[r], am[r]);
                fma2(acc[r][0], ab, kp0); fma2(acc[r][1], ab, kp1);
                fma2(acc[r][2], ab, kp2); fma2(acc[r][3], ab, kp3);
            }
        }
        __syncthreads();
    }

    #pragma unroll
    for (int r = 0; r < 8; r++) {
        int m = m0 + ty * 8 + r;
        #pragma unroll
        for (int c = 0; c < 4; c++) {
            int n = n0 + ((c < 2) ? (tx * 4 + 2 * c) : (64 + tx * 4 + 2 * (c - 2)));
            if (MODE == 0) {
                int b = m >> 10, i = m & 1023;
                float2 v = upk(acc[r][c]);
                if (n < 512) {
                    int hh = n >> 6, d = n & 63;
                    float* p = g_q + (((size_t)(b * 8 + hh) << 10) + i) * 64 + d;
                    p[0] = v.x; p[1] = v.y;
                } else if (n < 1024) {
                    int nn = n - 512, hh = nn >> 6, d = nn & 63;
                    float* p = g_kt + ((size_t)(b * 8 + hh) * 64 + d) * 1024 + i;
                    p[0] = v.x; p[1024] = v.y;
                } else {
                    int nn = n - 1024, hh = nn >> 6, d = nn & 63;
                    float* p = g_v + (((size_t)(b * 8 + hh) << 10) + i) * 64 + d;
                    p[0] = v.x; p[1] = v.y;
                }
            } else {
                ull bv = *(const ull*)(bias + n);
                *(ull*)(out + (size_t)m * 512 + n) = add2(acc[r][c], bv);
            }
        }
    }
}

// ======================= K2: pooling + selector (R4-proven) =======================
__global__ void __launch_bounds__(512) pool_kernel(const float* __restrict__ x) {
    const int b = blockIdx.x >> 3, s = blockIdx.x & 7;
    const int tid = threadIdx.x;
    const float* xb = x + ((size_t)b * 1024 + s * 128) * 512;
    float sum = 0.f;
    #pragma unroll 4
    for (int i = 0; i < 128; i++) sum += xb[(size_t)i * 512 + tid];
    g_part[(b * 8 + s) * 512 + tid] = sum;
}

__global__ void __launch_bounds__(512) selector(const float* __restrict__ W1,
                                                const float* __restrict__ b1,
                                                const float* __restrict__ W2,
                                                const float* __restrict__ b2,
                                                const float* __restrict__ logtau) {
    __shared__ float pooled[512];
    __shared__ float hh[256];
    __shared__ float lg[3];
    const int b = blockIdx.x, tid = threadIdx.x;
    {
        float s = 0.f;
        #pragma unroll
        for (int p = 0; p < 8; p++) s += g_part[(b * 8 + p) * 512 + tid];
        pooled[tid] = s * (1.0f / 1024.0f);
    }
    __syncthreads();
    if (tid < 256) {
        float a = b1[tid];
        const float* wr = W1 + (size_t)tid * 512;
        #pragma unroll 4
        for (int d = 0; d < 512; d++) a = fmaf(pooled[d], wr[d], a);
        hh[tid] = a > 0.f ? a : 0.f;
    }
    __syncthreads();
    if (tid < 3) {
        float a = b2[tid];
        const float* wr = W2 + (size_t)tid * 256;
        for (int d = 0; d < 256; d++) a = fmaf(hh[d], wr[d], a);
        lg[tid] = a;
    }
    __syncthreads();
    if (tid == 0) {
        float tau = expf(logtau[0]);
        tau = fminf(fmaxf(tau, 1e-4f), 10.0f);
        float l0 = lg[0] / tau, l1 = lg[1] / tau, l2 = lg[2] / tau;
        float mx = fmaxf(l0, fmaxf(l1, l2));
        float e0 = expf(l0 - mx), e1 = expf(l1 - mx), e2 = expf(l2 - mx);
        float inv = 1.0f / (e0 + e1 + e2);
        g_pw[b * 3 + 0] = e0 * inv;
        g_pw[b * 3 + 1] = e1 * inv;
        g_pw[b * 3 + 2] = e2 * inv;
    }
}

// ======================= K3: batched score GEMM  S = 0.125 * Q @ K^T =======================
__global__ void __launch_bounds__(256) scoreg() {
    __shared__ float As[16][132];
    __shared__ float Bs[16][132];
    const int bh = blockIdx.z;
    const int m0 = blockIdx.y * 128, n0 = blockIdx.x * 128;
    const int tid = threadIdx.x;
    const int tx = tid & 15, ty = tid >> 4;
    const float* qg  = g_q  + (size_t)bh * 65536;
    const float* ktg = g_kt + (size_t)bh * 65536;

    ull acc[8][4];
    #pragma unroll
    for (int r = 0; r < 8; r++)
        #pragma unroll
        for (int c = 0; c < 4; c++) acc[r][c] = 0ull;

    float4 pa[2], pb[2];
    auto ldT = [&](int k0) {
        #pragma unroll
        for (int i = 0; i < 2; i++) {
            int idx = tid + i * 256;
            pa[i] = *(const float4*)(qg  + (size_t)(m0 + (idx >> 2)) * 64 + k0 + (idx & 3) * 4);
            pb[i] = *(const float4*)(ktg + (size_t)(k0 + (idx >> 5)) * 1024 + n0 + (idx & 31) * 4);
        }
    };
    auto stT = [&]() {
        #pragma unroll
        for (int i = 0; i < 2; i++) {
            int idx = tid + i * 256;
            int r = idx >> 2, kq = (idx & 3) * 4;
            As[kq+0][r] = pa[i].x; As[kq+1][r] = pa[i].y;
            As[kq+2][r] = pa[i].z; As[kq+3][r] = pa[i].w;
            *(float4*)&Bs[idx >> 5][(idx & 31) * 4] = pb[i];
        }
    };

    ldT(0);
    for (int k0 = 0; k0 < 64; k0 += 16) {
        stT();
        __syncthreads();
        if (k0 < 48) ldT(k0 + 16);
        #pragma unroll
        for (int kk = 0; kk < 16; kk++) {
            ulonglong2 b0 = *(const ulonglong2*)&Bs[kk][tx * 4];
            ulonglong2 b1 = *(const ulonglong2*)&Bs[kk][64 + tx * 4];
            float4 av0 = *(const float4*)&As[kk][ty * 8];
            float4 av1 = *(const float4*)&As[kk][ty * 8 + 4];
            float am[8] = {av0.x, av0.y, av0.z, av0.w, av1.x, av1.y, av1.z, av1.w};
            #pragma unroll
            for (int r = 0; r < 8; r++) {
                ull ab = pk2(am[r], am[r]);
                fma2(acc[r][0], ab, b0.x); fma2(acc[r][1], ab, b0.y);
                fma2(acc[r][2], ab, b1.x); fma2(acc[r][3], ab, b1.y);
            }
        }
        if (k0 < 48) __syncthreads();
    }

    const ull sc2 = pk2(0.125f, 0.125f);
    #pragma unroll
    for (int r = 0; r < 8; r++) {
        size_t rowp = ((size_t)bh << 20) + (size_t)(m0 + ty * 8 + r) * 1024;
        float2 v0 = upk(mul2(acc[r][0], sc2));
        float2 v1 = upk(mul2(acc[r][1], sc2));
        float4 o0 = {v0.x, v0.y, v1.x, v1.y};
        *(float4*)(g_sc + rowp + n0 + tx * 4) = o0;
        float2 v2 = upk(mul2(acc[r][2], sc2));
        float2 v3 = upk(mul2(acc[r][3], sc2));
        float4 o1 = {v2.x, v2.y, v3.x, v3.y};
        *(float4*)(g_sc + rowp + n0 + 64 + tx * 4) = o1;
    }
}

// ======================= K4: mask + topk-threshold + softmax (in-place on g_sc) ================
struct SmemMS {
    float    sc[16][1032];     // 66 KB
    unsigned hist[16][256];    // 16 KB
    unsigned thr[16];
    float    rowmax[16];
    int      anyf[16];
};

__global__ void __launch_bounds__(512) masksm(const int* __restrict__ mask,
                                              const float* __restrict__ sparse_w,
                                              const float* __restrict__ sparse_b) {
    extern __shared__ char smraw[];
    SmemMS* sm = (SmemMS*)smraw;
    const int tid = threadIdx.x;
    const int i0 = blockIdx.x * 16;
    const int h  = blockIdx.y;
    const int b  = blockIdx.z;
    const int bh = b * 8 + h;
    float* scg = g_sc + ((size_t)bh << 20);

    const float pw0 = g_pw[b * 3 + 0], pw1 = g_pw[b * 3 + 1], pw2 = g_pw[b * 3 + 2];
    const float wsp = sparse_w[h], bsp = sparse_b[h];
    const bool need_smask = (((pw1 > 0.05f) != (pw1 + pw2 > 0.05f)) ||
                             ((pw0 + pw1 > 0.05f) != (pw0 + pw1 + pw2 > 0.05f)));

    // ---- load 16 rows of scores ----
    #pragma unroll
    for (int it = 0; it < 8; it++) {
        int idx = tid + it * 512;           // 0..4095 float4 slots
        int r = idx >> 8, jf = (idx & 255) * 4;
        *(float4*)&sm->sc[r][jf] = *(const float4*)(scg + (size_t)(i0 + r) * 1024 + jf);
    }
    __syncthreads();

    // ---- exact kth-largest per row: 16 warps, 1 row each ----
    if (need_smask) {
        const int wq = tid >> 5, lane = tid & 31;
        const int r = wq;
        unsigned prefix = 0;
        int kneed = KNEED;
        #pragma unroll
        for (int pass = 0; pass < 4; pass++) {
            const int shift = 24 - 8 * pass;
            #pragma unroll
            for (int q = 0; q < 8; q++) sm->hist[wq][lane * 8 + q] = 0u;
            __syncwarp();
            for (int t = 0; t < 32; t++) {
                int j = lane + t * 32;
                float s = fmaf(sm->sc[r][j], wsp, bsp);
                unsigned u = ordkey(s);
                bool cand;
                if (pass == 0) cand = true;
                else           cand = (((u ^ prefix) >> (shift + 8)) == 0u);
                int bucket = cand ? (int)((u >> shift) & 255u) : 256;
                unsigned mm = __match_any_sync(0xffffffffu, bucket);
                if ((__ffs(mm) - 1) == lane && bucket < 256)
                    atomicAdd(&sm->hist[wq][bucket], (unsigned)__popc(mm));
            }
            __syncwarp();
            const int base = 255 - lane * 8;
            int c[8]; int loc = 0;
            #pragma unroll
            for (int q = 0; q < 8; q++) { c[q] = (int)sm->hist[wq][base - q]; loc += c[q]; }
            int pre = loc;
            #pragma unroll
            for (int o = 1; o < 32; o <<= 1) {
                int v = __shfl_up_sync(0xffffffffu, pre, o);
                if (lane >= o) pre += v;
            }
            const int excl = pre - loc;
            const bool hit = (excl < kneed) && (kneed <= pre);
            const unsigned hb = __ballot_sync(0xffffffffu, hit);
            const int hl = __ffs(hb) - 1;
            int bsel = 0, kn2 = 0;
            if (hit) {
                int rem = kneed - excl;
                #pragma unroll
                for (int q = 0; q < 8; q++) {
                    if (rem <= c[q]) { bsel = base - q; kn2 = rem; break; }
                    rem -= c[q];
                }
            }
            bsel = __shfl_sync(0xffffffffu, bsel, hl);
            kn2  = __shfl_sync(0xffffffffu, kn2,  hl);
            prefix |= ((unsigned)bsel) << shift;
            kneed = kn2;
            __syncwarp();
        }
        if ((tid & 31) == 0) sm->thr[wq] = prefix;
    } else {
        if (tid < 16) sm->thr[tid] = 0u;
    }
    __syncthreads();

    // ---- combined mask + row max (one warp per row) ----
    const int r3 = tid >> 5;   // 0..15
    const int c3 = tid & 31;
    {
        const int* mrow = mask + b * 1024;
        const unsigned thrv = sm->thr[r3];
        const int ii = i0 + r3;
        float locmax = -3.0e38f;
        int any = 0;
        #pragma unroll
        for (int t = 0; t < 8; t++) {
            int j = c3 * 4 + t * 128;
            float4 f = *(const float4*)&sm->sc[r3][j];
            int4 mm4 = *(const int4*)(mrow + j);
            float fv[4] = {f.x, f.y, f.z, f.w};
            int   mv[4] = {mm4.x, mm4.y, mm4.z, mm4.w};
            #pragma unroll
            for (int e = 0; e < 4; e++) {
                int je = j + e;
                float s = fmaf(fv[e], wsp, bsp);
                float smv = (ordkey(s) >= thrv) ? 1.0f : 0.0f;
                float lcl = (je >= ii - 16 && je <= ii + 16) ? 1.0f : 0.0f;
                float comb = fmaf(pw0, lcl, fmaf(pw2, smv, pw1));
                bool keep = (comb > 0.05f) && (mv[e] != 0);
                if (keep) { locmax = fmaxf(locmax, fv[e]); any = 1; }
                else      fv[e] = NEGV;
            }
            float4 o = {fv[0], fv[1], fv[2], fv[3]};
            *(float4*)&sm->sc[r3][j] = o;
        }
        #pragma unroll
        for (int o = 16; o; o >>= 1) {
            locmax = fmaxf(locmax, __shfl_down_sync(0xffffffffu, locmax, o));
            any   |= __shfl_down_sync(0xffffffffu, any, o);
        }
        if (c3 == 0) { sm->rowmax[r3] = locmax; sm->anyf[r3] = any; }
    }
    __syncthreads();
    if (tid < 16) {
        if (!sm->anyf[tid]) { sm->sc[tid][0] = 0.0f; sm->rowmax[tid] = 0.0f; }
    }
    __syncthreads();

    // ---- exp + sum; write unnormalized P to gmem; 1/sum to g_inv ----
    {
        const float rmax = sm->rowmax[r3];
        float lsum = 0.f;
        #pragma unroll
        for (int t = 0; t < 8; t++) {
            int j = c3 * 4 + t * 128;
            float4 f = *(const float4*)&sm->sc[r3][j];
            f.x = __expf(f.x - rmax); f.y = __expf(f.y - rmax);
            f.z = __expf(f.z - rmax); f.w = __expf(f.w - rmax);
            *(float4*)(scg + (size_t)(i0 + r3) * 1024 + j) = f;
            lsum += (f.x + f.y) + (f.z + f.w);
        }
        #pragma unroll
        for (int o = 16; o; o >>= 1)
            lsum += __shfl_down_sync(0xffffffffu, lsum, o);
        if (c3 == 0) g_inv[bh * 1024 + i0 + r3] = 1.0f / lsum;
    }
}

// ======================= K5: batched AV GEMM  O = (P @ V) * inv =======================
__global__ void __launch_bounds__(128) avg_kernel() {
    __shared__ ull   As2[64][35];   // P rows duplicated as f32x2 pairs; pad 35 -> 2-way max
    __shared__ float Bs[32][68];    // V chunk
    const int bh = blockIdx.y;
    const int m0 = blockIdx.x * 64;
    const int tid = threadIdx.x;
    const int tx = tid & 7, ty = tid >> 3;   // ty 0..15: rows ty*4..+4; cols tx*4 & 32+tx*4
    const float* pg = g_sc + ((size_t)bh << 20);
    const float* vg = g_v + (size_t)bh * 65536;

    ull acc[4][4];
    #pragma unroll
    for (int r = 0; r < 4; r++)
        #pragma unroll
        for (int c = 0; c < 4; c++) acc[r][c] = 0ull;

    float4 pa[4], pv[4];
    auto ldT = [&](int k0) {
        #pragma unroll
        for (int it = 0; it < 4; it++) {
            int idx = tid + it * 128;   // 0..511
            pa[it] = *(const float4*)(pg + (size_t)(m0 + (idx >> 3)) * 1024 + k0 + (idx & 7) * 4);
            pv[it] = *(const float4*)(vg + (size_t)(k0 + (idx >> 4)) * 64 + (idx & 15) * 4);
        }
    };
    auto stT = [&]() {
        #pragma unroll
        for (int it = 0; it < 4; it++) {
            int idx = tid + it * 128;
            int r = idx >> 3, kq = (idx & 7) * 4;
            As2[r][kq+0] = pk2(pa[it].x, pa[it].x);
            As2[r][kq+1] = pk2(pa[it].y, pa[it].y);
            As2[r][kq+2] = pk2(pa[it].z, pa[it].z);
            As2[r][kq+3] = pk2(pa[it].w, pa[it].w);
            *(float4*)&Bs[idx >> 4][(idx & 15) * 4] = pv[it];
        }
    };

    ldT(0);
    for (int k0 = 0; k0 < 1024; k0 += 32) {
        stT();
        __syncthreads();
        if (k0 < 992) ldT(k0 + 32);
        #pragma unroll
        for (int kk = 0; kk < 32; kk++) {
            ulonglong2 b0 = *(const ulonglong2*)&Bs[kk][tx * 4];
            ulonglong2 b1 = *(const ulonglong2*)&Bs[kk][32 + tx * 4];
            #pragma unroll
            for (int r = 0; r < 4; r++) {
                ull aq = As2[ty * 4 + r][kk];
                fma2(acc[r][0], aq, b0.x); fma2(acc[r][1], aq, b0.y);
                fma2(acc[r][2], aq, b1.x); fma2(acc[r][3], aq, b1.y);
            }
        }
        if (k0 < 992) __syncthreads();
    }

    const int b = bh >> 3, h = bh & 7;
    #pragma unroll
    for (int r = 0; r < 4; r++) {
        int i = m0 + ty * 4 + r;
        float inv = g_inv[bh * 1024 + i];
        ull iv = pk2(inv, inv);
        float* op = g_ao + ((size_t)(b * 1024 + i)) * 512 + h * 64;
        float2 c0 = upk(mul2(acc[r][0], iv));
        float2 c1 = upk(mul2(acc[r][1], iv));
        float4 o0 = {c0.x, c0.y, c1.x, c1.y};
        *(float4*)(op + tx * 4) = o0;
        float2 c2 = upk(mul2(acc[r][2], iv));
        float2 c3f = upk(mul2(acc[r][3], iv));
        float4 o1 = {c2.x, c2.y, c3f.x, c3f.y};
        *(float4*)(op + 32 + tx * 4) = o1;
    }
}

// ======================= launch =======================
extern "C" void kernel_launch(void* const* d_in, const int* in_sizes, int n_in,
                              void* d_out, int out_size) {
    const float* x      = (const float*)d_in[0];
    const int*   mask   = (const int*)  d_in[1];
    const float* Wqkv   = (const float*)d_in[2];
    const float* Wproj  = (const float*)d_in[3];
    const float* bproj  = (const float*)d_in[4];
    const float* Wsel1  = (const float*)d_in[5];
    const float* bsel1  = (const float*)d_in[6];
    const float* Wsel2  = (const float*)d_in[7];
    const float* bsel2  = (const float*)d_in[8];
    const float* logtau = (const float*)d_in[9];
    const float* sw     = (const float*)d_in[10];
    const float* sb     = (const float*)d_in[11];
    float* out = (float*)d_out;

    static int smem_set = 0;
    if (!smem_set) {
        cudaFuncSetAttribute(masksm, cudaFuncAttributeMaxDynamicSharedMemorySize,
                             (int)sizeof(SmemMS));
        smem_set = 1;
    }

    gemm128<0><<<dim3(12, 32), 256>>>(x, Wqkv, nullptr, nullptr);
    pool_kernel<<<32, 512>>>(x);
    selector<<<4, 512>>>(Wsel1, bsel1, Wsel2, bsel2, logtau);
    scoreg<<<dim3(8, 8, 32), 256>>>();
    masksm<<<dim3(64, 8, 4), 512, sizeof(SmemMS)>>>(mask, sw, sb);
    avg_kernel<<<dim3(16, 32), 128>>>();
    gemm128<1><<<dim3(4, 32), 256>>>(nullptr, Wproj, bproj, out);
}